// round 3
// baseline (speedup 1.0000x reference)
#include <cuda_runtime.h>
#include <math.h>

#define WPB 12            // warps per block
#define PPW 8             // points per warp
#define NTHREADS (WPB*32)
#define WPAD 68           // padded row stride (floats) -> conflict-free LDS.128

// fixed problem geometry
#define C_STRIDE 2097152ULL     // 256*256*32
#define B_STRIDE 67108864ULL    // 32*256*256*32
#define I_STRIDE 8192           // 256*32
#define J_STRIDE 32

struct __align__(16) Smem {
  float Wzh[64][WPAD], Wrh[64][WPAD], Wqh[64][WPAD];   // h-parts (cols 0..63)
  float Wzx[64][WPAD], Wrx[64][WPAD], Wqx[64][WPAD];   // x-parts (cols 64..127)
  float Wd1h[32][WPAD], Wd1x[32][WPAD];
  float bz[64], br[64], bq[64], bd1[32];
  float Wd2[3][32];
  float bd2[4];
  float h[WPB*PPW][64];   // per-point hidden state
  float g[WPB*PPW][64];   // scratch: x during precompute, r*h during iters, hmid at end
};

__device__ __forceinline__ float fast_sigmoid(float x) {
  return __fdividef(1.0f, 1.0f + __expf(-x));
}
__device__ __forceinline__ float fast_tanh(float x) {
  return __fdividef(2.0f, 1.0f + __expf(-2.0f * x)) - 1.0f;
}

__device__ __forceinline__ void dot4(float& acc, const float4 wv, const float4 vv) {
  acc = fmaf(wv.x, vv.x, acc);
  acc = fmaf(wv.y, vv.y, acc);
  acc = fmaf(wv.z, vv.z, acc);
  acc = fmaf(wv.w, vv.w, acc);
}

__global__ __launch_bounds__(NTHREADS, 1)
void gru_decoder_kernel(
    const float* __restrict__ before, const float* __restrict__ after,
    const float* __restrict__ pf, const int* __restrict__ coords,
    const float* __restrict__ Wz, const float* __restrict__ bz,
    const float* __restrict__ Wr, const float* __restrict__ br,
    const float* __restrict__ Wq, const float* __restrict__ bq,
    const float* __restrict__ Wd1, const float* __restrict__ bd1,
    const float* __restrict__ Wd2, const float* __restrict__ bd2,
    float* __restrict__ out, int N, int total_pts)
{
  extern __shared__ char smem_raw[];
  Smem& s = *reinterpret_cast<Smem*>(smem_raw);

  const int tid = threadIdx.x;

  // ---- load + split weights into shared (once per block) ----
  for (int idx = tid; idx < 64 * 64; idx += NTHREADS) {
    int t = idx >> 6, k = idx & 63;
    s.Wzh[t][k] = Wz[t * 128 + k];      s.Wzx[t][k] = Wz[t * 128 + 64 + k];
    s.Wrh[t][k] = Wr[t * 128 + k];      s.Wrx[t][k] = Wr[t * 128 + 64 + k];
    s.Wqh[t][k] = Wq[t * 128 + k];      s.Wqx[t][k] = Wq[t * 128 + 64 + k];
  }
  for (int idx = tid; idx < 32 * 64; idx += NTHREADS) {
    int t = idx >> 6, k = idx & 63;
    s.Wd1h[t][k] = Wd1[t * 128 + k];    s.Wd1x[t][k] = Wd1[t * 128 + 64 + k];
  }
  if (tid < 64) { s.bz[tid] = bz[tid]; s.br[tid] = br[tid]; s.bq[tid] = bq[tid]; }
  if (tid < 32) s.bd1[tid] = bd1[tid];
  if (tid < 96) ((float*)s.Wd2)[tid] = Wd2[tid];
  if (tid < 3)  s.bd2[tid] = bd2[tid];
  __syncthreads();

  const int warp = tid >> 5, lane = tid & 31;
  const int P0 = warp * PPW;
  const int nchunks = (total_pts + PPW - 1) / PPW;
  const int gwarps = gridDim.x * WPB;

  for (int cid = blockIdx.x * WPB + warp; cid < nchunks; cid += gwarps) {
    const int base = cid * PPW;

    // ---- per-point coords (lanes 0..7), broadcast via shuffle ----
    int sp_me = 0, b_me = 0;
    if (lane < PPW) {
      int pg = base + lane;
      if (pg >= total_pts) pg = total_pts - 1;
      const int* cc = coords + (size_t)pg * 3;      // coords are int32 (JAX x64 off)
      sp_me = cc[0] * I_STRIDE + cc[1] * J_STRIDE + cc[2];
      b_me = pg / N;
    }

    // ---- gather h (before||after) and load x into g ----
#pragma unroll
    for (int p = 0; p < PPW; p++) {
      int sp = __shfl_sync(0xffffffffu, sp_me, p);
      int bb = __shfl_sync(0xffffffffu, b_me, p);
      size_t ofs = (size_t)bb * B_STRIDE + (size_t)lane * C_STRIDE + (unsigned)sp;
      s.h[P0 + p][lane]      = __ldg(before + ofs);
      s.h[P0 + p][lane + 32] = __ldg(after + ofs);
      int pg = base + p; if (pg >= total_pts) pg = total_pts - 1;
      const float* xr = pf + (size_t)pg * 64;
      s.g[P0 + p][lane]      = __ldg(xr + lane);
      s.g[P0 + p][lane + 32] = __ldg(xr + lane + 32);
    }
    __syncwarp();

    // ---- precompute x-projections: pass 1 (zx, rx) ----
    float zx0[PPW], zx1[PPW], rx0[PPW], rx1[PPW];
#pragma unroll
    for (int p = 0; p < PPW; p++) {
      zx0[p] = s.bz[lane]; zx1[p] = s.bz[lane + 32];
      rx0[p] = s.br[lane]; rx1[p] = s.br[lane + 32];
    }
#pragma unroll 4
    for (int k4 = 0; k4 < 16; k4++) {
      float4 a0 = *(const float4*)&s.Wzx[lane][k4 * 4];
      float4 a1 = *(const float4*)&s.Wzx[lane + 32][k4 * 4];
      float4 c0 = *(const float4*)&s.Wrx[lane][k4 * 4];
      float4 c1 = *(const float4*)&s.Wrx[lane + 32][k4 * 4];
#pragma unroll
      for (int p = 0; p < PPW; p++) {
        float4 xv = *(const float4*)&s.g[P0 + p][k4 * 4];
        dot4(zx0[p], a0, xv); dot4(zx1[p], a1, xv);
        dot4(rx0[p], c0, xv); dot4(rx1[p], c1, xv);
      }
    }

    // ---- precompute x-projections: pass 2 (qx, d1x) ----
    float qx0[PPW], qx1[PPW], dx[PPW];
#pragma unroll
    for (int p = 0; p < PPW; p++) {
      qx0[p] = s.bq[lane]; qx1[p] = s.bq[lane + 32]; dx[p] = s.bd1[lane];
    }
#pragma unroll 4
    for (int k4 = 0; k4 < 16; k4++) {
      float4 a0 = *(const float4*)&s.Wqx[lane][k4 * 4];
      float4 a1 = *(const float4*)&s.Wqx[lane + 32][k4 * 4];
      float4 d0 = *(const float4*)&s.Wd1x[lane][k4 * 4];
#pragma unroll
      for (int p = 0; p < PPW; p++) {
        float4 xv = *(const float4*)&s.g[P0 + p][k4 * 4];
        dot4(qx0[p], a0, xv); dot4(qx1[p], a1, xv); dot4(dx[p], d0, xv);
      }
    }
    __syncwarp();   // all lanes done reading x from g before g is reused for r*h

    // ---- 4 GRU iterations ----
#pragma unroll 1
    for (int it = 0; it < 4; it++) {
      float az0[PPW], az1[PPW], ar0[PPW], ar1[PPW];
#pragma unroll
      for (int p = 0; p < PPW; p++) {
        az0[p] = zx0[p]; az1[p] = zx1[p]; ar0[p] = rx0[p]; ar1[p] = rx1[p];
      }
#pragma unroll 4
      for (int k4 = 0; k4 < 16; k4++) {
        float4 a0 = *(const float4*)&s.Wzh[lane][k4 * 4];
        float4 a1 = *(const float4*)&s.Wzh[lane + 32][k4 * 4];
        float4 c0 = *(const float4*)&s.Wrh[lane][k4 * 4];
        float4 c1 = *(const float4*)&s.Wrh[lane + 32][k4 * 4];
#pragma unroll
        for (int p = 0; p < PPW; p++) {
          float4 hv = *(const float4*)&s.h[P0 + p][k4 * 4];
          dot4(az0[p], a0, hv); dot4(az1[p], a1, hv);
          dot4(ar0[p], c0, hv); dot4(ar1[p], c1, hv);
        }
      }
      float zz0[PPW], zz1[PPW];
#pragma unroll
      for (int p = 0; p < PPW; p++) {
        zz0[p] = fast_sigmoid(az0[p]);
        zz1[p] = fast_sigmoid(az1[p]);
        float r0 = fast_sigmoid(ar0[p]);
        float r1 = fast_sigmoid(ar1[p]);
        s.g[P0 + p][lane]      = r0 * s.h[P0 + p][lane];
        s.g[P0 + p][lane + 32] = r1 * s.h[P0 + p][lane + 32];
      }
      __syncwarp();

      float aq0[PPW], aq1[PPW];
#pragma unroll
      for (int p = 0; p < PPW; p++) { aq0[p] = qx0[p]; aq1[p] = qx1[p]; }
#pragma unroll 4
      for (int k4 = 0; k4 < 16; k4++) {
        float4 a0 = *(const float4*)&s.Wqh[lane][k4 * 4];
        float4 a1 = *(const float4*)&s.Wqh[lane + 32][k4 * 4];
#pragma unroll
        for (int p = 0; p < PPW; p++) {
          float4 gv = *(const float4*)&s.g[P0 + p][k4 * 4];
          dot4(aq0[p], a0, gv); dot4(aq1[p], a1, gv);
        }
      }
#pragma unroll
      for (int p = 0; p < PPW; p++) {
        float q0 = fast_tanh(aq0[p]);
        float q1 = fast_tanh(aq1[p]);
        float h0 = s.h[P0 + p][lane];
        float h1 = s.h[P0 + p][lane + 32];
        h0 = fmaf(zz0[p], q0 - h0, h0);   // (1-z)h + zq
        h1 = fmaf(zz1[p], q1 - h1, h1);
        s.h[P0 + p][lane]      = h0;
        s.h[P0 + p][lane + 32] = h1;
      }
      __syncwarp();
    }

    // ---- decoder: hmid = gelu(Wd1h@h + d1x), each lane owns one of 32 outputs ----
    float am[PPW];
#pragma unroll
    for (int p = 0; p < PPW; p++) am[p] = dx[p];
#pragma unroll 4
    for (int k4 = 0; k4 < 16; k4++) {
      float4 d0 = *(const float4*)&s.Wd1h[lane][k4 * 4];
#pragma unroll
      for (int p = 0; p < PPW; p++) {
        float4 hv = *(const float4*)&s.h[P0 + p][k4 * 4];
        dot4(am[p], d0, hv);
      }
    }
#pragma unroll
    for (int p = 0; p < PPW; p++) {
      float v = am[p];
      s.g[P0 + p][lane] = 0.5f * v * (1.0f + erff(v * 0.70710678118654752f));
    }
    __syncwarp();

    // ---- flow = Wd2 @ hmid + bd2 (3 outputs) ----
    if (lane < 3) {
#pragma unroll
      for (int p = 0; p < PPW; p++) {
        if (base + p < total_pts) {
          float acc = s.bd2[lane];
#pragma unroll
          for (int m = 0; m < 32; m++)
            acc = fmaf(s.Wd2[lane][m], s.g[P0 + p][m], acc);
          out[(size_t)(base + p) * 3 + lane] = acc;
        }
      }
    }
    __syncwarp();
  }
}

extern "C" void kernel_launch(void* const* d_in, const int* in_sizes, int n_in,
                              void* d_out, int out_size) {
  const float* before = (const float*)d_in[0];
  const float* after  = (const float*)d_in[1];
  const float* pf     = (const float*)d_in[2];
  const int*   coords = (const int*)d_in[3];     // int32 (JAX x64 disabled)
  const float* Wz  = (const float*)d_in[4];
  const float* bz  = (const float*)d_in[5];
  const float* Wr  = (const float*)d_in[6];
  const float* br  = (const float*)d_in[7];
  const float* Wq  = (const float*)d_in[8];
  const float* bq  = (const float*)d_in[9];
  const float* Wd1 = (const float*)d_in[10];
  const float* bd1 = (const float*)d_in[11];
  const float* Wd2 = (const float*)d_in[12];
  const float* bd2 = (const float*)d_in[13];
  float* out = (float*)d_out;

  int B = in_sizes[0] / (int)(32u * 256u * 256u * 32u);
  if (B < 1) B = 1;
  int total_pts = in_sizes[3] / 3;      // coords has B*N*3 elements
  int N = total_pts / B;

  cudaFuncSetAttribute(gru_decoder_kernel,
                       cudaFuncAttributeMaxDynamicSharedMemorySize,
                       (int)sizeof(Smem));

  gru_decoder_kernel<<<152, NTHREADS, sizeof(Smem)>>>(
      before, after, pf, coords, Wz, bz, Wr, br, Wq, bq,
      Wd1, bd1, Wd2, bd2, out, N, total_pts);
}